// round 11
// baseline (speedup 1.0000x reference)
#include <cuda_runtime.h>
#include <math.h>

// Problem constants
#define BB   4
#define CIN  128
#define HH   96
#define WWW  96
#define OO   128
#define PP   9216      // H*W
#define PT   64        // pixel tile per block
#define NPT  144       // PP / PT

typedef unsigned long long ull;

// Scratch (device globals — no allocation allowed)
__device__ float g_off [BB * 18 * PP];     // (b, 2k+d, p)
__device__ float g_mask[BB * 9  * PP];     // (b, k, p) — sigmoid applied
__device__ float g_wt  [9 * CIN * OO];     // (k, c, o)  transposed deform_w
__device__ float g_owt [9 * CIN * 32];     // (k, c, slot) transposed offset/mask w

// ---- packed fp32x2 helpers (Blackwell FFMA2) --------------------------------
__device__ __forceinline__ void fma2(ull& d, ull a, ull b) {
    asm("fma.rn.f32x2 %0, %1, %2, %0;" : "+l"(d) : "l"(a), "l"(b));
}
__device__ __forceinline__ ull dup2(float w) {
    ull r;
    asm("mov.b64 %0, {%1, %1};" : "=l"(r) : "r"(__float_as_uint(w)));
    return r;
}
__device__ __forceinline__ float2 unpack2(ull v) {
    unsigned lo, hi;
    asm("mov.b64 {%0, %1}, %2;" : "=r"(lo), "=r"(hi) : "l"(v));
    return make_float2(__uint_as_float(lo), __uint_as_float(hi));
}

// ---------------------------------------------------------------------------
// Kernel 0: one-time weight transposes so GEMM-side access is broadcast/coalesced.
// ---------------------------------------------------------------------------
__global__ __launch_bounds__(256) void transpose_w_kernel(
    const float* __restrict__ dw,
    const float* __restrict__ ow,
    const float* __restrict__ mw)
{
    int i = blockIdx.x * 256 + threadIdx.x;
    if (i < 9 * CIN * OO) {
        int o = i & 127, c = (i >> 7) & 127, k = i >> 14;
        g_wt[i] = dw[(o * CIN + c) * 9 + k];
    }
    if (i < 9 * CIN * 32) {
        int s = i & 31, c = (i >> 5) & 127, k = i >> 12;
        float w = 0.f;
        if (s < 18)      w = ow[(s * CIN + c) * 9 + k];
        else if (s < 27) w = mw[((s - 18) * CIN + c) * 9 + k];
        g_owt[i] = w;
    }
}

// ---------------------------------------------------------------------------
// Kernel 1: offset conv (18ch) + mask conv (9ch, sigmoid), fused implicit GEMM
//   Y[32slots, 64p] = W[32,1152] @ Im2col[1152,64]
// 9 phases (one per tap): stage 128c x 64p im2col slab, then 128 rank-1 steps
// with weights read directly from gmem (L1 broadcast).
// ---------------------------------------------------------------------------
__global__ __launch_bounds__(256, 4) void offmask_kernel(
    const float* __restrict__ x2,
    const float* __restrict__ offset_b, const float* __restrict__ mask_b)
{
    __shared__ __align__(16) float vsm[CIN][64];   // 32KB

    const int tid = threadIdx.x;
    const int b  = blockIdx.y;
    const int p0 = blockIdx.x * PT;
    const int tx = tid & 15;
    const int ty = tid >> 4;
    const int vpl = tid & 63;
    const int vho = (p0 + vpl) / WWW, vwo = (p0 + vpl) % WWW;
    const int ccb = tid >> 6;

    ull acc2[2][2] = {{0ull,0ull},{0ull,0ull}};

    for (int k = 0; k < 9; k++) {
        const int ky = k / 3, kx = k % 3;
        __syncthreads();
        // ---- stage im2col slab: 128c x 64p, 32 values per thread ----
        {
            int y = vho - 1 + ky, x = vwo - 1 + kx;
            bool ok = (unsigned)y < (unsigned)HH && (unsigned)x < (unsigned)WWW;
            const float* bp = x2 + (size_t)(b * CIN) * PP + y * WWW + x;
#pragma unroll 8
            for (int r = 0; r < 32; r++) {
                int cc = ccb + r * 4;
                vsm[cc][vpl] = ok ? bp[(size_t)cc * PP] : 0.f;
            }
        }
        __syncthreads();
        // ---- math: 128 rank-1 updates, weights via gmem broadcast ----
        const float* wk = g_owt + (size_t)k * CIN * 32 + ty * 2;
#pragma unroll 8
        for (int cc = 0; cc < CIN; cc++) {
            float2 w = __ldg((const float2*)(wk + cc * 32));
            ulonglong2 v = *(const ulonglong2*)&vsm[cc][tx * 4];
            ull w0 = dup2(w.x), w1 = dup2(w.y);
            fma2(acc2[0][0], w0, v.x);
            fma2(acc2[0][1], w0, v.y);
            fma2(acc2[1][0], w1, v.x);
            fma2(acc2[1][1], w1, v.y);
        }
    }

    // epilogue: bias; sigmoid for mask channels
#pragma unroll
    for (int i = 0; i < 2; i++) {
        int oc = ty * 2 + i;
        float a[4];
        float2 lo = unpack2(acc2[i][0]);
        float2 hi = unpack2(acc2[i][1]);
        a[0] = lo.x; a[1] = lo.y; a[2] = hi.x; a[3] = hi.y;
#pragma unroll
        for (int j = 0; j < 4; j++) {
            int p = p0 + tx * 4 + j;
            if (oc < 18) {
                g_off[(b * 18 + oc) * PP + p] = a[j] + offset_b[oc];
            } else if (oc < 27) {
                float sg = a[j] + mask_b[oc - 18];
                g_mask[(b * 9 + (oc - 18)) * PP + p] = 1.f / (1.f + expf(-sg));
            }
        }
    }
}

// ---------------------------------------------------------------------------
// Kernel 2: modulated deformable conv v2 as implicit GEMM:
//   out[128o, 64p] = W[128, 1152] @ V[1152, 64]
// 9 phases: stage the full 128c x 64p bilinear-sampled slab for tap k (deep
// MLP gather batch), then 128 rank-1 steps with weights read directly from
// gmem (2-address L1 broadcast, slice is L1-hot). 18 barriers total; no
// weight smem -> 3 CTAs/SM.
// ---------------------------------------------------------------------------
__global__ __launch_bounds__(256, 3) void deform_kernel(
    const float* __restrict__ x,
    const float* __restrict__ deform_b,
    float* __restrict__ out)
{
    __shared__ __align__(16) int   sidx[9][64][4];   // 9KB
    __shared__ __align__(16) float swt [9][64][4];   // 9KB
    __shared__ __align__(16) float vsm [CIN][64];    // 32KB

    const int tid = threadIdx.x;
    const int b  = blockIdx.y;
    const int p0 = blockIdx.x * PT;
    const int tx = tid & 15;        // -> 4 pixels
    const int ty = tid >> 4;        // -> 8 out channels
    const int vpl = tid & 63;
    const int ccb = tid >> 6;

    // ---- precompute bilinear corner metadata for 64 pixels x 9 taps ----
    for (int idx = tid; idx < 9 * 64; idx += 256) {
        int k = idx >> 6, pl = idx & 63;
        int p  = p0 + pl;
        int ho = p / WWW, wo = p % WWW;
        int ky = k / 3, kx = k % 3;
        float dy = g_off[(b * 18 + 2 * k    ) * PP + p];
        float dx = g_off[(b * 18 + 2 * k + 1) * PP + p];
        float m  = g_mask[(b * 9 + k) * PP + p];
        float py = (float)(ho - 1 + ky) + dy;
        float px = (float)(wo - 1 + kx) + dx;
        float fy = floorf(py), fx = floorf(px);
        int y0 = (int)fy, x0 = (int)fx;
        int y1 = y0 + 1,  x1 = x0 + 1;
        float ly = py - fy, lx = px - fx;
        float hy = 1.f - ly, hx = 1.f - lx;
        bool vy0 = (unsigned)y0 < (unsigned)HH, vy1 = (unsigned)y1 < (unsigned)HH;
        bool vx0 = (unsigned)x0 < (unsigned)WWW, vx1 = (unsigned)x1 < (unsigned)WWW;
        bool v00 = vy0 && vx0, v01 = vy0 && vx1, v10 = vy1 && vx0, v11 = vy1 && vx1;
        sidx[k][pl][0] = v00 ? (y0 * WWW + x0) : 0;
        sidx[k][pl][1] = v01 ? (y0 * WWW + x1) : 0;
        sidx[k][pl][2] = v10 ? (y1 * WWW + x0) : 0;
        sidx[k][pl][3] = v11 ? (y1 * WWW + x1) : 0;
        swt[k][pl][0] = v00 ? hy * hx * m : 0.f;
        swt[k][pl][1] = v01 ? hy * lx * m : 0.f;
        swt[k][pl][2] = v10 ? ly * hx * m : 0.f;
        swt[k][pl][3] = v11 ? ly * lx * m : 0.f;
    }

    ull acc2[8][2];
#pragma unroll
    for (int i = 0; i < 8; i++) { acc2[i][0] = 0ull; acc2[i][1] = 0ull; }

    for (int k = 0; k < 9; k++) {
        __syncthreads();
        // ---- gather phase: 128c x 64p sampled slab, 32 values/thread ----
        {
            int4   id = *(const int4*)  &sidx[k][vpl][0];
            float4 wq = *(const float4*)&swt [k][vpl][0];
            const float* bp = x + (size_t)(b * CIN + ccb) * PP;
#pragma unroll 4
            for (int r = 0; r < 32; r++) {
                const float* base = bp + (size_t)(r * 4) * PP;
                float v = wq.x * base[id.x];
                v = fmaf(wq.y, base[id.y], v);
                v = fmaf(wq.z, base[id.z], v);
                v = fmaf(wq.w, base[id.w], v);
                vsm[ccb + r * 4][vpl] = v;
            }
        }
        __syncthreads();
        // ---- math phase: 128 rank-1 updates of 8oc x 4p, weights via gmem ----
        const float* wk = g_wt + (size_t)k * CIN * OO + ty * 8;
#pragma unroll 8
        for (int cc = 0; cc < CIN; cc++) {
            float4 wa = __ldg((const float4*)(wk + cc * OO));
            float4 wb = __ldg((const float4*)(wk + cc * OO + 4));
            ulonglong2 v = *(const ulonglong2*)&vsm[cc][tx * 4];
            ull w0 = dup2(wa.x), w1 = dup2(wa.y), w2 = dup2(wa.z), w3 = dup2(wa.w);
            ull w4 = dup2(wb.x), w5 = dup2(wb.y), w6 = dup2(wb.z), w7 = dup2(wb.w);
            fma2(acc2[0][0], w0, v.x);  fma2(acc2[0][1], w0, v.y);
            fma2(acc2[1][0], w1, v.x);  fma2(acc2[1][1], w1, v.y);
            fma2(acc2[2][0], w2, v.x);  fma2(acc2[2][1], w2, v.y);
            fma2(acc2[3][0], w3, v.x);  fma2(acc2[3][1], w3, v.y);
            fma2(acc2[4][0], w4, v.x);  fma2(acc2[4][1], w4, v.y);
            fma2(acc2[5][0], w5, v.x);  fma2(acc2[5][1], w5, v.y);
            fma2(acc2[6][0], w6, v.x);  fma2(acc2[6][1], w6, v.y);
            fma2(acc2[7][0], w7, v.x);  fma2(acc2[7][1], w7, v.y);
        }
    }

    // epilogue: bias + vectorized store
#pragma unroll
    for (int i = 0; i < 8; i++) {
        int oc = ty * 8 + i;
        float bias = deform_b[oc];
        float2 lo = unpack2(acc2[i][0]);
        float2 hi = unpack2(acc2[i][1]);
        float4 o;
        o.x = lo.x + bias;
        o.y = lo.y + bias;
        o.z = hi.x + bias;
        o.w = hi.y + bias;
        *(float4*)&out[(size_t)(b * OO + oc) * PP + p0 + tx * 4] = o;
    }
}

// ---------------------------------------------------------------------------
extern "C" void kernel_launch(void* const* d_in, const int* in_sizes, int n_in,
                              void* d_out, int out_size)
{
    const float* x        = (const float*)d_in[0];
    const float* x2       = (const float*)d_in[1];
    const float* offset_w = (const float*)d_in[2];
    const float* offset_b = (const float*)d_in[3];
    const float* mask_w   = (const float*)d_in[4];
    const float* mask_b   = (const float*)d_in[5];
    const float* deform_w = (const float*)d_in[6];
    const float* deform_b = (const float*)d_in[7];
    float* out = (float*)d_out;

    transpose_w_kernel<<<(9 * CIN * OO + 255) / 256, 256>>>(deform_w, offset_w, mask_w);
    dim3 grid(NPT, BB);
    offmask_kernel<<<grid, 256>>>(x2, offset_b, mask_b);
    deform_kernel<<<grid, 256>>>(x, deform_b, out);
}

// round 14
// speedup vs baseline: 1.3915x; 1.3915x over previous
#include <cuda_runtime.h>
#include <math.h>

// Problem constants
#define BB   4
#define CIN  128
#define HH   96
#define WWW  96
#define OO   128
#define PP   9216      // H*W
#define PT   64        // pixel tile per block
#define NPT  144       // PP / PT

typedef unsigned long long ull;

// Scratch (device globals — no allocation allowed)
__device__ float g_off [BB * 18 * PP];     // (b, 2k+d, p)
__device__ float g_mask[BB * 9  * PP];     // (b, k, p) — sigmoid applied
__device__ float g_wt  [9 * CIN * OO];     // (k, c, o)  transposed deform_w
__device__ float g_owt [9 * CIN * 32];     // (k, c, slot) transposed offset/mask w

// ---- packed fp32x2 helpers (Blackwell FFMA2) --------------------------------
__device__ __forceinline__ void fma2(ull& d, ull a, ull b) {
    asm("fma.rn.f32x2 %0, %1, %2, %0;" : "+l"(d) : "l"(a), "l"(b));
}
__device__ __forceinline__ ull dup2(float w) {
    ull r;
    asm("mov.b64 %0, {%1, %1};" : "=l"(r) : "r"(__float_as_uint(w)));
    return r;
}
__device__ __forceinline__ float2 unpack2(ull v) {
    unsigned lo, hi;
    asm("mov.b64 {%0, %1}, %2;" : "=r"(lo), "=r"(hi) : "l"(v));
    return make_float2(__uint_as_float(lo), __uint_as_float(hi));
}

// ---------------------------------------------------------------------------
// Kernel 0: one-time weight transposes so GEMM staging is coalesced.
// ---------------------------------------------------------------------------
__global__ __launch_bounds__(256) void transpose_w_kernel(
    const float* __restrict__ dw,
    const float* __restrict__ ow,
    const float* __restrict__ mw)
{
    int i = blockIdx.x * 256 + threadIdx.x;
    if (i < 9 * CIN * OO) {
        int o = i & 127, c = (i >> 7) & 127, k = i >> 14;
        g_wt[i] = dw[(o * CIN + c) * 9 + k];
    }
    if (i < 9 * CIN * 32) {
        int s = i & 31, c = (i >> 5) & 127, k = i >> 12;
        float w = 0.f;
        if (s < 18)      w = ow[(s * CIN + c) * 9 + k];
        else if (s < 27) w = mw[((s - 18) * CIN + c) * 9 + k];
        g_owt[i] = w;
    }
}

// ---------------------------------------------------------------------------
// Kernel 1: offset conv (18ch) + mask conv (9ch, sigmoid), fused implicit GEMM
//   Y[32slots, 64p] = W[32,1152] @ Im2col[1152,64]
// Double-buffered, ONE barrier per chunk: stage ch+1, math ch, sync.
// ---------------------------------------------------------------------------
__global__ __launch_bounds__(256) void offmask_kernel(
    const float* __restrict__ x2,
    const float* __restrict__ offset_b, const float* __restrict__ mask_b)
{
    __shared__ __align__(16) float wsm[2][16][32];   // 4KB
    __shared__ __align__(16) float vsm[2][16][64];   // 8KB

    const int tid = threadIdx.x;
    const int b  = blockIdx.y;
    const int p0 = blockIdx.x * PT;
    const int tx = tid & 15;
    const int ty = tid >> 4;
    const int vpl = tid & 63;
    const int vho = (p0 + vpl) / WWW, vwo = (p0 + vpl) % WWW;

    ull acc2[2][2] = {{0ull,0ull},{0ull,0ull}};

    // stage chunk 0 into buffer 0
    {
#pragma unroll
        for (int r = 0; r < 2; r++) {
            int idx = tid + r * 256;
            int cc = idx >> 5, oc = idx & 31;
            wsm[0][cc][oc] = g_owt[(0 * CIN + cc) * 32 + oc];
        }
#pragma unroll
        for (int r = 0; r < 4; r++) {
            int cc = (tid + r * 256) >> 6;
            int y = vho - 1, x = vwo - 1;
            float v = 0.f;
            if ((unsigned)y < (unsigned)HH && (unsigned)x < (unsigned)WWW)
                v = x2[((b * CIN + cc) * HH + y) * WWW + x];
            vsm[0][cc][vpl] = v;
        }
        __syncthreads();
    }

    for (int ch = 0; ch < 72; ch++) {
        const int s = ch & 1;
        // ---- stage chunk ch+1 into buffer s^1 (LDGs fly during math) ----
        if (ch < 71) {
            const int nk = (ch + 1) >> 3, ncb = (ch + 1) & 7;
            const int nky = nk / 3, nkx = nk % 3, nc0 = ncb * 16;
#pragma unroll
            for (int r = 0; r < 2; r++) {
                int idx = tid + r * 256;
                int cc = idx >> 5, oc = idx & 31;
                wsm[s ^ 1][cc][oc] = g_owt[(nk * CIN + nc0 + cc) * 32 + oc];
            }
            int y = vho - 1 + nky, x = vwo - 1 + nkx;
            bool ok = (unsigned)y < (unsigned)HH && (unsigned)x < (unsigned)WWW;
            const float* bp = x2 + (size_t)(b * CIN + nc0) * PP + y * WWW + x;
#pragma unroll
            for (int r = 0; r < 4; r++) {
                int cc = (tid + r * 256) >> 6;
                vsm[s ^ 1][cc][vpl] = ok ? bp[(size_t)cc * PP] : 0.f;
            }
        }
        // ---- math on buffer s ----
#pragma unroll
        for (int cc = 0; cc < 16; cc++) {
            float2 w = *(const float2*)&wsm[s][cc][ty * 2];
            ulonglong2 v = *(const ulonglong2*)&vsm[s][cc][tx * 4];
            ull w0 = dup2(w.x), w1 = dup2(w.y);
            fma2(acc2[0][0], w0, v.x);
            fma2(acc2[0][1], w0, v.y);
            fma2(acc2[1][0], w1, v.x);
            fma2(acc2[1][1], w1, v.y);
        }
        __syncthreads();
    }

    // epilogue: bias; sigmoid for mask channels
#pragma unroll
    for (int i = 0; i < 2; i++) {
        int oc = ty * 2 + i;
        float a[4];
        float2 lo = unpack2(acc2[i][0]);
        float2 hi = unpack2(acc2[i][1]);
        a[0] = lo.x; a[1] = lo.y; a[2] = hi.x; a[3] = hi.y;
#pragma unroll
        for (int j = 0; j < 4; j++) {
            int p = p0 + tx * 4 + j;
            if (oc < 18) {
                g_off[(b * 18 + oc) * PP + p] = a[j] + offset_b[oc];
            } else if (oc < 27) {
                float sg = a[j] + mask_b[oc - 18];
                g_mask[(b * 9 + (oc - 18)) * PP + p] = 1.f / (1.f + expf(-sg));
            }
        }
    }
}

// ---------------------------------------------------------------------------
// Kernel 2: modulated deformable conv v2 as implicit GEMM:
//   out[128o, 64p] = W[128, 1152] @ V[1152, 64]
// Double-buffered, ONE barrier per chunk: stage ch+1 (LDG issued first),
// math on ch while loads are in flight, single sync.
// ---------------------------------------------------------------------------
__global__ __launch_bounds__(256) void deform_kernel(
    const float* __restrict__ x,
    const float* __restrict__ deform_b,
    float* __restrict__ out)
{
    __shared__ __align__(16) int   sidx[9][64][4];    // 9KB
    __shared__ __align__(16) float swt [9][64][4];    // 9KB
    __shared__ __align__(16) float wsm[2][16][128];   // 16KB
    __shared__ __align__(16) float vsm[2][16][64];    // 8KB

    const int tid = threadIdx.x;
    const int b  = blockIdx.y;
    const int p0 = blockIdx.x * PT;
    const int tx = tid & 15;        // -> 4 pixels
    const int ty = tid >> 4;        // -> 8 out channels
    const int vpl = tid & 63;

    // ---- precompute bilinear corner metadata for 64 pixels x 9 taps ----
    for (int idx = tid; idx < 9 * 64; idx += 256) {
        int k = idx >> 6, pl = idx & 63;
        int p  = p0 + pl;
        int ho = p / WWW, wo = p % WWW;
        int ky = k / 3, kx = k % 3;
        float dy = g_off[(b * 18 + 2 * k    ) * PP + p];
        float dx = g_off[(b * 18 + 2 * k + 1) * PP + p];
        float m  = g_mask[(b * 9 + k) * PP + p];
        float py = (float)(ho - 1 + ky) + dy;
        float px = (float)(wo - 1 + kx) + dx;
        float fy = floorf(py), fx = floorf(px);
        int y0 = (int)fy, x0 = (int)fx;
        int y1 = y0 + 1,  x1 = x0 + 1;
        float ly = py - fy, lx = px - fx;
        float hy = 1.f - ly, hx = 1.f - lx;
        bool vy0 = (unsigned)y0 < (unsigned)HH, vy1 = (unsigned)y1 < (unsigned)HH;
        bool vx0 = (unsigned)x0 < (unsigned)WWW, vx1 = (unsigned)x1 < (unsigned)WWW;
        bool v00 = vy0 && vx0, v01 = vy0 && vx1, v10 = vy1 && vx0, v11 = vy1 && vx1;
        sidx[k][pl][0] = v00 ? (y0 * WWW + x0) : 0;
        sidx[k][pl][1] = v01 ? (y0 * WWW + x1) : 0;
        sidx[k][pl][2] = v10 ? (y1 * WWW + x0) : 0;
        sidx[k][pl][3] = v11 ? (y1 * WWW + x1) : 0;
        swt[k][pl][0] = v00 ? hy * hx * m : 0.f;
        swt[k][pl][1] = v01 ? hy * lx * m : 0.f;
        swt[k][pl][2] = v10 ? ly * hx * m : 0.f;
        swt[k][pl][3] = v11 ? ly * lx * m : 0.f;
    }
    __syncthreads();

    ull acc2[8][2];
#pragma unroll
    for (int i = 0; i < 8; i++) { acc2[i][0] = 0ull; acc2[i][1] = 0ull; }

    // ---- stage chunk 0 into buffer 0 ----
    {
#pragma unroll
        for (int r = 0; r < 2; r++) {
            int idx = tid + r * 256;
            int cc = idx >> 5, o4 = (idx & 31) * 4;
            *(float4*)&wsm[0][cc][o4] = *(const float4*)&g_wt[cc * OO + o4];
        }
        int4   id = *(const int4*)  &sidx[0][vpl][0];
        float4 wq = *(const float4*)&swt [0][vpl][0];
#pragma unroll
        for (int r = 0; r < 4; r++) {
            int cc = (tid + r * 256) >> 6;
            const float* base = x + (size_t)(b * CIN + cc) * PP;
            float v = wq.x * base[id.x];
            v = fmaf(wq.y, base[id.y], v);
            v = fmaf(wq.z, base[id.z], v);
            v = fmaf(wq.w, base[id.w], v);
            vsm[0][cc][vpl] = v;
        }
        __syncthreads();
    }

    for (int ch = 0; ch < 72; ch++) {
        const int s = ch & 1;
        // ---- stage chunk ch+1 into buffer s^1 (LDGs issued before math) ----
        if (ch < 71) {
            const int nk = (ch + 1) >> 3, ncb = (ch + 1) & 7;
            const int nc0 = ncb * 16;
#pragma unroll
            for (int r = 0; r < 2; r++) {
                int idx = tid + r * 256;
                int cc = idx >> 5, o4 = (idx & 31) * 4;
                *(float4*)&wsm[s ^ 1][cc][o4] =
                    *(const float4*)&g_wt[(nk * CIN + nc0 + cc) * OO + o4];
            }
            int4   id = *(const int4*)  &sidx[nk][vpl][0];
            float4 wq = *(const float4*)&swt [nk][vpl][0];
            const float* bp = x + (size_t)(b * CIN + nc0) * PP;
#pragma unroll
            for (int r = 0; r < 4; r++) {
                int cc = (tid + r * 256) >> 6;
                const float* base = bp + (size_t)cc * PP;
                float v = wq.x * base[id.x];
                v = fmaf(wq.y, base[id.y], v);
                v = fmaf(wq.z, base[id.z], v);
                v = fmaf(wq.w, base[id.w], v);
                vsm[s ^ 1][cc][vpl] = v;
            }
        }
        // ---- math on buffer s: 16 rank-1 updates of 8oc x 4p ----
#pragma unroll
        for (int cc = 0; cc < 16; cc++) {
            float4 wa = *(const float4*)&wsm[s][cc][ty * 8];
            float4 wb = *(const float4*)&wsm[s][cc][ty * 8 + 4];
            ulonglong2 v = *(const ulonglong2*)&vsm[s][cc][tx * 4];
            ull w0 = dup2(wa.x), w1 = dup2(wa.y), w2 = dup2(wa.z), w3 = dup2(wa.w);
            ull w4 = dup2(wb.x), w5 = dup2(wb.y), w6 = dup2(wb.z), w7 = dup2(wb.w);
            fma2(acc2[0][0], w0, v.x);  fma2(acc2[0][1], w0, v.y);
            fma2(acc2[1][0], w1, v.x);  fma2(acc2[1][1], w1, v.y);
            fma2(acc2[2][0], w2, v.x);  fma2(acc2[2][1], w2, v.y);
            fma2(acc2[3][0], w3, v.x);  fma2(acc2[3][1], w3, v.y);
            fma2(acc2[4][0], w4, v.x);  fma2(acc2[4][1], w4, v.y);
            fma2(acc2[5][0], w5, v.x);  fma2(acc2[5][1], w5, v.y);
            fma2(acc2[6][0], w6, v.x);  fma2(acc2[6][1], w6, v.y);
            fma2(acc2[7][0], w7, v.x);  fma2(acc2[7][1], w7, v.y);
        }
        __syncthreads();
    }

    // epilogue: bias + vectorized store
#pragma unroll
    for (int i = 0; i < 8; i++) {
        int oc = ty * 8 + i;
        float bias = deform_b[oc];
        float2 lo = unpack2(acc2[i][0]);
        float2 hi = unpack2(acc2[i][1]);
        float4 o;
        o.x = lo.x + bias;
        o.y = lo.y + bias;
        o.z = hi.x + bias;
        o.w = hi.y + bias;
        *(float4*)&out[(size_t)(b * OO + oc) * PP + p0 + tx * 4] = o;
    }
}

// ---------------------------------------------------------------------------
extern "C" void kernel_launch(void* const* d_in, const int* in_sizes, int n_in,
                              void* d_out, int out_size)
{
    const float* x        = (const float*)d_in[0];
    const float* x2       = (const float*)d_in[1];
    const float* offset_w = (const float*)d_in[2];
    const float* offset_b = (const float*)d_in[3];
    const float* mask_w   = (const float*)d_in[4];
    const float* mask_b   = (const float*)d_in[5];
    const float* deform_w = (const float*)d_in[6];
    const float* deform_b = (const float*)d_in[7];
    float* out = (float*)d_out;

    transpose_w_kernel<<<(9 * CIN * OO + 255) / 256, 256>>>(deform_w, offset_w, mask_w);
    dim3 grid(NPT, BB);
    offmask_kernel<<<grid, 256>>>(x2, offset_b, mask_b);
    deform_kernel<<<grid, 256>>>(x, deform_b, out);
}

// round 15
// speedup vs baseline: 1.4922x; 1.0724x over previous
#include <cuda_runtime.h>
#include <math.h>

// Problem constants
#define BB   4
#define CIN  128
#define HH   96
#define WWW  96
#define OO   128
#define PP   9216      // H*W
#define PT   64        // pixel tile per block
#define NPT  144       // PP / PT
#define CCH  32        // c-rows per chunk
#define NCH  36        // 9*128 / CCH

typedef unsigned long long ull;

// Scratch (device globals — no allocation allowed)
__device__ float g_off [BB * 18 * PP];     // (b, 2k+d, p)
__device__ float g_mask[BB * 9  * PP];     // (b, k, p) — sigmoid applied
__device__ float g_wt  [9 * CIN * OO];     // (k, c, o)  transposed deform_w
__device__ float g_owt [9 * CIN * 32];     // (k, c, slot) transposed offset/mask w

// ---- packed fp32x2 helpers (Blackwell FFMA2) --------------------------------
__device__ __forceinline__ void fma2(ull& d, ull a, ull b) {
    asm("fma.rn.f32x2 %0, %1, %2, %0;" : "+l"(d) : "l"(a), "l"(b));
}
__device__ __forceinline__ ull dup2(float w) {
    ull r;
    asm("mov.b64 %0, {%1, %1};" : "=l"(r) : "r"(__float_as_uint(w)));
    return r;
}
__device__ __forceinline__ float2 unpack2(ull v) {
    unsigned lo, hi;
    asm("mov.b64 {%0, %1}, %2;" : "=r"(lo), "=r"(hi) : "l"(v));
    return make_float2(__uint_as_float(lo), __uint_as_float(hi));
}

// ---------------------------------------------------------------------------
// Kernel 0: one-time weight transposes so GEMM staging is coalesced.
// ---------------------------------------------------------------------------
__global__ __launch_bounds__(256) void transpose_w_kernel(
    const float* __restrict__ dw,
    const float* __restrict__ ow,
    const float* __restrict__ mw)
{
    int i = blockIdx.x * 256 + threadIdx.x;
    if (i < 9 * CIN * OO) {
        int o = i & 127, c = (i >> 7) & 127, k = i >> 14;
        g_wt[i] = dw[(o * CIN + c) * 9 + k];
    }
    if (i < 9 * CIN * 32) {
        int s = i & 31, c = (i >> 5) & 127, k = i >> 12;
        float w = 0.f;
        if (s < 18)      w = ow[(s * CIN + c) * 9 + k];
        else if (s < 27) w = mw[((s - 18) * CIN + c) * 9 + k];
        g_owt[i] = w;
    }
}

// ---------------------------------------------------------------------------
// Kernel 1: offset conv (18ch) + mask conv (9ch, sigmoid), fused implicit GEMM
//   Y[32slots, 64p] = W[32,1152] @ Im2col[1152,64]
// Double-buffered, 32-row chunks, ONE barrier per chunk (18 barriers total).
// ---------------------------------------------------------------------------
__global__ __launch_bounds__(256) void offmask_kernel(
    const float* __restrict__ x2,
    const float* __restrict__ offset_b, const float* __restrict__ mask_b)
{
    __shared__ __align__(16) float wsm[2][CCH][32];   // 8KB
    __shared__ __align__(16) float vsm[2][CCH][64];   // 16KB

    const int tid = threadIdx.x;
    const int b  = blockIdx.y;
    const int p0 = blockIdx.x * PT;
    const int tx = tid & 15;
    const int ty = tid >> 4;
    const int vpl = tid & 63;
    const int vho = (p0 + vpl) / WWW, vwo = (p0 + vpl) % WWW;

    ull acc2[2][2] = {{0ull,0ull},{0ull,0ull}};

    // stage chunk 0 into buffer 0 (k=0, c0=0)
    {
#pragma unroll
        for (int r = 0; r < 4; r++) {
            int idx = tid + r * 256;
            int cc = idx >> 5, oc = idx & 31;
            wsm[0][cc][oc] = g_owt[cc * 32 + oc];
        }
        int y = vho - 1, x = vwo - 1;
        bool ok = (unsigned)y < (unsigned)HH && (unsigned)x < (unsigned)WWW;
        const float* bp = x2 + (size_t)(b * CIN) * PP + y * WWW + x;
#pragma unroll
        for (int r = 0; r < 8; r++) {
            int cc = (tid >> 6) + r * 4;
            vsm[0][cc][vpl] = ok ? bp[(size_t)cc * PP] : 0.f;
        }
        __syncthreads();
    }

    for (int ch = 0; ch < NCH; ch++) {
        const int s = ch & 1;
        // ---- stage chunk ch+1 into buffer s^1 (LDGs fly during math) ----
        if (ch < NCH - 1) {
            const int nk = (ch + 1) >> 2, ncb = (ch + 1) & 3;
            const int nky = nk / 3, nkx = nk % 3, nc0 = ncb * CCH;
#pragma unroll
            for (int r = 0; r < 4; r++) {
                int idx = tid + r * 256;
                int cc = idx >> 5, oc = idx & 31;
                wsm[s ^ 1][cc][oc] = g_owt[(nk * CIN + nc0 + cc) * 32 + oc];
            }
            int y = vho - 1 + nky, x = vwo - 1 + nkx;
            bool ok = (unsigned)y < (unsigned)HH && (unsigned)x < (unsigned)WWW;
            const float* bp = x2 + (size_t)(b * CIN + nc0) * PP + y * WWW + x;
#pragma unroll
            for (int r = 0; r < 8; r++) {
                int cc = (tid >> 6) + r * 4;
                vsm[s ^ 1][cc][vpl] = ok ? bp[(size_t)cc * PP] : 0.f;
            }
        }
        // ---- math on buffer s ----
#pragma unroll
        for (int cc = 0; cc < CCH; cc++) {
            float2 w = *(const float2*)&wsm[s][cc][ty * 2];
            ulonglong2 v = *(const ulonglong2*)&vsm[s][cc][tx * 4];
            ull w0 = dup2(w.x), w1 = dup2(w.y);
            fma2(acc2[0][0], w0, v.x);
            fma2(acc2[0][1], w0, v.y);
            fma2(acc2[1][0], w1, v.x);
            fma2(acc2[1][1], w1, v.y);
        }
        __syncthreads();
    }

    // epilogue: bias; sigmoid for mask channels
#pragma unroll
    for (int i = 0; i < 2; i++) {
        int oc = ty * 2 + i;
        float a[4];
        float2 lo = unpack2(acc2[i][0]);
        float2 hi = unpack2(acc2[i][1]);
        a[0] = lo.x; a[1] = lo.y; a[2] = hi.x; a[3] = hi.y;
#pragma unroll
        for (int j = 0; j < 4; j++) {
            int p = p0 + tx * 4 + j;
            if (oc < 18) {
                g_off[(b * 18 + oc) * PP + p] = a[j] + offset_b[oc];
            } else if (oc < 27) {
                float sg = a[j] + mask_b[oc - 18];
                g_mask[(b * 9 + (oc - 18)) * PP + p] = 1.f / (1.f + expf(-sg));
            }
        }
    }
}

// ---------------------------------------------------------------------------
// Kernel 2: modulated deformable conv v2 as implicit GEMM:
//   out[128o, 64p] = W[128, 1152] @ V[1152, 64]
// Double-buffered, 32-row chunks, ONE barrier per chunk (36 barriers total).
// ---------------------------------------------------------------------------
__global__ __launch_bounds__(256) void deform_kernel(
    const float* __restrict__ x,
    const float* __restrict__ deform_b,
    float* __restrict__ out)
{
    __shared__ __align__(16) int   sidx[9][64][4];     // 9KB
    __shared__ __align__(16) float swt [9][64][4];     // 9KB
    __shared__ __align__(16) float wsm[2][CCH][128];   // 32KB
    __shared__ __align__(16) float vsm[2][CCH][64];    // 16KB

    const int tid = threadIdx.x;
    const int b  = blockIdx.y;
    const int p0 = blockIdx.x * PT;
    const int tx = tid & 15;        // -> 4 pixels
    const int ty = tid >> 4;        // -> 8 out channels
    const int vpl = tid & 63;

    // ---- precompute bilinear corner metadata for 64 pixels x 9 taps ----
    for (int idx = tid; idx < 9 * 64; idx += 256) {
        int k = idx >> 6, pl = idx & 63;
        int p  = p0 + pl;
        int ho = p / WWW, wo = p % WWW;
        int ky = k / 3, kx = k % 3;
        float dy = g_off[(b * 18 + 2 * k    ) * PP + p];
        float dx = g_off[(b * 18 + 2 * k + 1) * PP + p];
        float m  = g_mask[(b * 9 + k) * PP + p];
        float py = (float)(ho - 1 + ky) + dy;
        float px = (float)(wo - 1 + kx) + dx;
        float fy = floorf(py), fx = floorf(px);
        int y0 = (int)fy, x0 = (int)fx;
        int y1 = y0 + 1,  x1 = x0 + 1;
        float ly = py - fy, lx = px - fx;
        float hy = 1.f - ly, hx = 1.f - lx;
        bool vy0 = (unsigned)y0 < (unsigned)HH, vy1 = (unsigned)y1 < (unsigned)HH;
        bool vx0 = (unsigned)x0 < (unsigned)WWW, vx1 = (unsigned)x1 < (unsigned)WWW;
        bool v00 = vy0 && vx0, v01 = vy0 && vx1, v10 = vy1 && vx0, v11 = vy1 && vx1;
        sidx[k][pl][0] = v00 ? (y0 * WWW + x0) : 0;
        sidx[k][pl][1] = v01 ? (y0 * WWW + x1) : 0;
        sidx[k][pl][2] = v10 ? (y1 * WWW + x0) : 0;
        sidx[k][pl][3] = v11 ? (y1 * WWW + x1) : 0;
        swt[k][pl][0] = v00 ? hy * hx * m : 0.f;
        swt[k][pl][1] = v01 ? hy * lx * m : 0.f;
        swt[k][pl][2] = v10 ? ly * hx * m : 0.f;
        swt[k][pl][3] = v11 ? ly * lx * m : 0.f;
    }
    __syncthreads();

    ull acc2[8][2];
#pragma unroll
    for (int i = 0; i < 8; i++) { acc2[i][0] = 0ull; acc2[i][1] = 0ull; }

    // ---- stage chunk 0 into buffer 0 (k=0, c0=0) ----
    {
#pragma unroll
        for (int r = 0; r < 4; r++) {
            int idx = tid + r * 256;
            int cc = idx >> 5, o4 = (idx & 31) * 4;
            *(float4*)&wsm[0][cc][o4] = *(const float4*)&g_wt[cc * OO + o4];
        }
        int4   id = *(const int4*)  &sidx[0][vpl][0];
        float4 wq = *(const float4*)&swt [0][vpl][0];
        const float* bp = x + (size_t)(b * CIN) * PP;
#pragma unroll
        for (int r = 0; r < 8; r++) {
            int cc = (tid >> 6) + r * 4;
            const float* base = bp + (size_t)cc * PP;
            float v = wq.x * base[id.x];
            v = fmaf(wq.y, base[id.y], v);
            v = fmaf(wq.z, base[id.z], v);
            v = fmaf(wq.w, base[id.w], v);
            vsm[0][cc][vpl] = v;
        }
        __syncthreads();
    }

    for (int ch = 0; ch < NCH; ch++) {
        const int s = ch & 1;
        // ---- stage chunk ch+1 into buffer s^1 (LDGs issued before math) ----
        if (ch < NCH - 1) {
            const int nk = (ch + 1) >> 2, ncb = (ch + 1) & 3;
            const int nc0 = ncb * CCH;
#pragma unroll
            for (int r = 0; r < 4; r++) {
                int idx = tid + r * 256;
                int cc = idx >> 5, o4 = (idx & 31) * 4;
                *(float4*)&wsm[s ^ 1][cc][o4] =
                    *(const float4*)&g_wt[(nk * CIN + nc0 + cc) * OO + o4];
            }
            int4   id = *(const int4*)  &sidx[nk][vpl][0];
            float4 wq = *(const float4*)&swt [nk][vpl][0];
            const float* bp = x + (size_t)(b * CIN + nc0) * PP;
#pragma unroll
            for (int r = 0; r < 8; r++) {
                int cc = (tid >> 6) + r * 4;
                const float* base = bp + (size_t)cc * PP;
                float v = wq.x * base[id.x];
                v = fmaf(wq.y, base[id.y], v);
                v = fmaf(wq.z, base[id.z], v);
                v = fmaf(wq.w, base[id.w], v);
                vsm[s ^ 1][cc][vpl] = v;
            }
        }
        // ---- math on buffer s: 32 rank-1 updates of 8oc x 4p ----
#pragma unroll
        for (int cc = 0; cc < CCH; cc++) {
            float4 wa = *(const float4*)&wsm[s][cc][ty * 8];
            float4 wb = *(const float4*)&wsm[s][cc][ty * 8 + 4];
            ulonglong2 v = *(const ulonglong2*)&vsm[s][cc][tx * 4];
            ull w0 = dup2(wa.x), w1 = dup2(wa.y), w2 = dup2(wa.z), w3 = dup2(wa.w);
            ull w4 = dup2(wb.x), w5 = dup2(wb.y), w6 = dup2(wb.z), w7 = dup2(wb.w);
            fma2(acc2[0][0], w0, v.x);  fma2(acc2[0][1], w0, v.y);
            fma2(acc2[1][0], w1, v.x);  fma2(acc2[1][1], w1, v.y);
            fma2(acc2[2][0], w2, v.x);  fma2(acc2[2][1], w2, v.y);
            fma2(acc2[3][0], w3, v.x);  fma2(acc2[3][1], w3, v.y);
            fma2(acc2[4][0], w4, v.x);  fma2(acc2[4][1], w4, v.y);
            fma2(acc2[5][0], w5, v.x);  fma2(acc2[5][1], w5, v.y);
            fma2(acc2[6][0], w6, v.x);  fma2(acc2[6][1], w6, v.y);
            fma2(acc2[7][0], w7, v.x);  fma2(acc2[7][1], w7, v.y);
        }
        __syncthreads();
    }

    // epilogue: bias + vectorized store
#pragma unroll
    for (int i = 0; i < 8; i++) {
        int oc = ty * 8 + i;
        float bias = deform_b[oc];
        float2 lo = unpack2(acc2[i][0]);
        float2 hi = unpack2(acc2[i][1]);
        float4 o;
        o.x = lo.x + bias;
        o.y = lo.y + bias;
        o.z = hi.x + bias;
        o.w = hi.y + bias;
        *(float4*)&out[(size_t)(b * OO + oc) * PP + p0 + tx * 4] = o;
    }
}

// ---------------------------------------------------------------------------
extern "C" void kernel_launch(void* const* d_in, const int* in_sizes, int n_in,
                              void* d_out, int out_size)
{
    const float* x        = (const float*)d_in[0];
    const float* x2       = (const float*)d_in[1];
    const float* offset_w = (const float*)d_in[2];
    const float* offset_b = (const float*)d_in[3];
    const float* mask_w   = (const float*)d_in[4];
    const float* mask_b   = (const float*)d_in[5];
    const float* deform_w = (const float*)d_in[6];
    const float* deform_b = (const float*)d_in[7];
    float* out = (float*)d_out;

    transpose_w_kernel<<<(9 * CIN * OO + 255) / 256, 256>>>(deform_w, offset_w, mask_w);
    dim3 grid(NPT, BB);
    offmask_kernel<<<grid, 256>>>(x2, offset_b, mask_b);
    deform_kernel<<<grid, 256>>>(x, deform_b, out);
}